// round 15
// baseline (speedup 1.0000x reference)
#include <cuda_runtime.h>
#include <cuda_fp16.h>
#include <cstdint>

// ============================================================
// DST-II y[16384,1024], 3-level Cooley-Tukey:
//  Stage1: P/Q[rp][b] = sum_a x[32a+b]*{sin,cos}(pi a rp/32)
//  Stage2 (rank-factored): m = 64c+R, V1 = Q*cB - sgn*P*sB,
//    V2 = Q*sB + sgn*P*cB; y = sum_b sinA*V1 + cosA*V2.
// R15: compact basis builder (44x32, 1 slot/thread, ~1us vs 4.9us);
//      fused kernel = R14 (mirror-rp pairing, 4 CTAs/SM).
// ============================================================

#define BATCH   16384
#define SIGS    8
#define THREADS 128
#define PQ_PITCH 1040

// smem layout (bytes)
#define SM_X    0          // x: [s8][a32][b32] fp16 pitch 80 = 20480 B; later y-staging fp16
#define SM_PQ   20480      // [rp33]{[s8] rows of 128B, XOR-chunk swizzle}, pitch 1040
#define SMEM_TOTAL (SM_PQ + 33 * PQ_PITCH)   // 54800

// gmem scratch (pre-packed fragments / tables)
__device__ uint4 g_Wf[4 * 2 * 32];   // stage-1 W A-fragments
__device__ uint4 g_A3[4 * 32];       // stage-2 A-table fragments [ks4][lane32]
__device__ uint4 g_beta[64 * 16];    // [R-1][tbl4][t4]; tbl: 0=cB 1=-sgn*sB 2=sB 3=sgn*cB

// ---------------- helpers ----------------
__device__ __forceinline__ uint32_t smem_u32(const void* p) {
    uint32_t a;
    asm("{ .reg .u64 t; cvta.to.shared.u64 t, %1; cvt.u32.u64 %0, t; }" : "=r"(a) : "l"(p));
    return a;
}
__device__ __forceinline__ void ldm_x4(uint32_t* r, uint32_t addr) {
    asm volatile("ldmatrix.sync.aligned.m8n8.x4.shared.b16 {%0,%1,%2,%3}, [%4];\n"
                 : "=r"(r[0]), "=r"(r[1]), "=r"(r[2]), "=r"(r[3]) : "r"(addr));
}
__device__ __forceinline__ void ldm_x4_t(uint32_t* r, uint32_t addr) {
    asm volatile("ldmatrix.sync.aligned.m8n8.x4.trans.shared.b16 {%0,%1,%2,%3}, [%4];\n"
                 : "=r"(r[0]), "=r"(r[1]), "=r"(r[2]), "=r"(r[3]) : "r"(addr));
}
__device__ __forceinline__ void mma_16816(float* c, const uint32_t* a, const uint32_t* b) {
    asm volatile(
        "mma.sync.aligned.m16n8k16.row.col.f32.f16.f16.f32 "
        "{%0,%1,%2,%3}, {%4,%5,%6,%7}, {%8,%9}, {%0,%1,%2,%3};\n"
        : "+f"(c[0]), "+f"(c[1]), "+f"(c[2]), "+f"(c[3])
        : "r"(a[0]), "r"(a[1]), "r"(a[2]), "r"(a[3]), "r"(b[0]), "r"(b[1]));
}
__device__ __forceinline__ void sts32(uint32_t addr, uint32_t v) {
    asm volatile("st.shared.b32 [%0], %1;\n" :: "r"(addr), "r"(v));
}
__device__ __forceinline__ void sts128(uint32_t addr, uint32_t a, uint32_t b,
                                       uint32_t c, uint32_t d) {
    asm volatile("st.shared.v4.b32 [%0], {%1,%2,%3,%4};\n"
                 :: "r"(addr), "r"(a), "r"(b), "r"(c), "r"(d));
}
__device__ __forceinline__ void lds64(uint32_t addr, uint32_t& lo, uint32_t& hi) {
    asm volatile("ld.shared.v2.b32 {%0,%1}, [%2];\n" : "=r"(lo), "=r"(hi) : "r"(addr));
}
__device__ __forceinline__ uint32_t pk2(float a, float b) {
    __half2 h = __floats2half2_rn(a, b);
    return *reinterpret_cast<uint32_t*>(&h);
}
__device__ __forceinline__ __half2 h2(uint32_t u) { return *reinterpret_cast<__half2*>(&u); }
__device__ __forceinline__ uint32_t u32(__half2 h) { return *reinterpret_cast<uint32_t*>(&h); }

// ============================================================
// Basis values
// ============================================================
__device__ __forceinline__ float w_val(int f, int a) {  // f = 2rp+pq
    int rp = f >> 1, pq = f & 1;
    if (rp > 32) return 0.0f;
    int mm = pq ? ((a * rp + 16) & 63) : ((a * rp) & 63);
    return sinpif((float)mm * (1.0f / 32.0f));
}
__device__ __forceinline__ float w2_val(int fp, int a) {
    int f = (fp == 63) ? 65 : fp + 1;
    return w_val(f, a);
}
// stage-2 A-table: k' = v*32 + b; v=0 -> sin(c(2b+1)pi/32), v=1 -> cos
__device__ __forceinline__ float a3_val(int c, int kp) {
    int v = kp >> 5, b = kp & 31;
    int ang = (c * (2 * b + 1) + (v ? 16 : 0)) & 63;
    return sinpif((float)ang * (1.0f / 32.0f));
}
// beta tables
__device__ __forceinline__ float beta_val(int R, int tbl, int b) {
    int angB = ((2 * b + 1) * R) & 4095;
    float sB = sinpif((float)angB * (1.0f / 2048.0f));
    float cB = sinpif((float)((angB + 1024) & 4095) * (1.0f / 2048.0f));
    float sgn = (R <= 32) ? 1.0f : -1.0f;
    switch (tbl) {
        case 0:  return cB;
        case 1:  return -sgn * sB;
        case 2:  return sB;
        default: return sgn * cB;
    }
}

// ============================================================
// Compact basis builder: 44 blocks x 32 threads, 1 uint4 slot/thread.
// Slots: [0,256) Wf, [256,384) A3, [384,1408) beta.
// ============================================================
__global__ void build_basis_kernel() {
    int gid = blockIdx.x * 32 + threadIdx.x;   // 0..1407
    if (gid < 256) {
        int mi = gid >> 6, ks = (gid >> 5) & 1, l = gid & 31;
        int r0 = l >> 2, k0 = 16 * ks + 2 * (l & 3);
        uint4 o;
        o.x = pk2(w2_val(mi * 16 + r0,     k0),     w2_val(mi * 16 + r0,     k0 + 1));
        o.y = pk2(w2_val(mi * 16 + 8 + r0, k0),     w2_val(mi * 16 + 8 + r0, k0 + 1));
        o.z = pk2(w2_val(mi * 16 + r0,     k0 + 8), w2_val(mi * 16 + r0,     k0 + 9));
        o.w = pk2(w2_val(mi * 16 + 8 + r0, k0 + 8), w2_val(mi * 16 + 8 + r0, k0 + 9));
        g_Wf[(mi * 2 + ks) * 32 + l] = o;
    } else if (gid < 384) {
        int idx = gid - 256;
        int ks = idx >> 5, l = idx & 31;
        int g = l >> 2, t4 = l & 3;
        int k0 = 16 * ks + 2 * t4;
        uint4 o;
        o.x = pk2(a3_val(g,     k0),     a3_val(g,     k0 + 1));
        o.y = pk2(a3_val(g + 8, k0),     a3_val(g + 8, k0 + 1));
        o.z = pk2(a3_val(g,     k0 + 8), a3_val(g,     k0 + 9));
        o.w = pk2(a3_val(g + 8, k0 + 8), a3_val(g + 8, k0 + 9));
        g_A3[ks * 32 + l] = o;
    } else {
        int idx = gid - 384;              // 0..1023
        int R   = (idx >> 4) + 1;         // 1..64
        int tbl = (idx >> 2) & 3;
        int t4  = idx & 3;
        uint4 o;
        o.x = pk2(beta_val(R, tbl, 2 * t4),      beta_val(R, tbl, 2 * t4 + 1));
        o.y = pk2(beta_val(R, tbl, 8 + 2 * t4),  beta_val(R, tbl, 9 + 2 * t4));
        o.z = pk2(beta_val(R, tbl, 16 + 2 * t4), beta_val(R, tbl, 17 + 2 * t4));
        o.w = pk2(beta_val(R, tbl, 24 + 2 * t4), beta_val(R, tbl, 25 + 2 * t4));
        g_beta[(R - 1) * 16 + tbl * 4 + t4] = o;
    }
}

// ============================================================
// Per-residue V + MMA worker: acc += [A_sin,A_cos] . V(beta(R), bq)
// ============================================================
__device__ __forceinline__ void residue_mma(float* acc, const uint32_t* bq,
                                            const uint4* A3, int R, int t4) {
    const uint4* bp = g_beta + (size_t)(R - 1) * 16 + t4;
    uint32_t v[8];
    {   // V1 = P*(-sgn sB) + Q*cB
        uint4 cB   = __ldg(bp);
        uint4 nsBp = __ldg(bp + 4);
        v[0] = u32(__hfma2(h2(bq[0]), h2(nsBp.x), __hmul2(h2(bq[4]), h2(cB.x))));
        v[1] = u32(__hfma2(h2(bq[1]), h2(nsBp.y), __hmul2(h2(bq[5]), h2(cB.y))));
        v[2] = u32(__hfma2(h2(bq[2]), h2(nsBp.z), __hmul2(h2(bq[6]), h2(cB.z))));
        v[3] = u32(__hfma2(h2(bq[3]), h2(nsBp.w), __hmul2(h2(bq[7]), h2(cB.w))));
    }
    {   // V2 = P*(sgn cB) + Q*sB
        uint4 sB  = __ldg(bp + 8);
        uint4 cBp = __ldg(bp + 12);
        v[4] = u32(__hfma2(h2(bq[0]), h2(cBp.x), __hmul2(h2(bq[4]), h2(sB.x))));
        v[5] = u32(__hfma2(h2(bq[1]), h2(cBp.y), __hmul2(h2(bq[5]), h2(sB.y))));
        v[6] = u32(__hfma2(h2(bq[2]), h2(cBp.z), __hmul2(h2(bq[6]), h2(sB.z))));
        v[7] = u32(__hfma2(h2(bq[3]), h2(cBp.w), __hmul2(h2(bq[7]), h2(sB.w))));
    }
    uint32_t a0[4] = { A3[0].x, A3[0].y, A3[0].z, A3[0].w };
    mma_16816(acc, a0, v);
    uint32_t a1[4] = { A3[1].x, A3[1].y, A3[1].z, A3[1].w };
    mma_16816(acc, a1, v + 2);
    uint32_t a2[4] = { A3[2].x, A3[2].y, A3[2].z, A3[2].w };
    mma_16816(acc, a2, v + 4);
    uint32_t a3[4] = { A3[3].x, A3[3].y, A3[3].z, A3[3].w };
    mma_16816(acc, a3, v + 6);
}

// ============================================================
// Main fused kernel: 8 signals / CTA, 128 threads (4 warps), 4 CTAs/SM.
// ============================================================
__global__ void __launch_bounds__(THREADS, 4)
dst_fused_kernel(const float* __restrict__ x, float* __restrict__ y) {
    extern __shared__ char smem[];
    const uint32_t sb = smem_u32(smem);
    const int tid  = threadIdx.x;
    const int wid  = tid >> 5;          // 0..3
    const int lane = tid & 31;
    const size_t s_base = (size_t)blockIdx.x * SIGS;

    // ---- per-warp x load: signals 2wid, 2wid+1 (fp32 -> fp16, pitch 80) ----
    float4 xv0[8], xv1[8];
    {
        const float4* xs0 = reinterpret_cast<const float4*>(x + (s_base + 2 * wid) * 1024);
        const float4* xs1 = reinterpret_cast<const float4*>(x + (s_base + 2 * wid + 1) * 1024);
        #pragma unroll
        for (int i = 0; i < 8; i++) xv0[i] = xs0[i * 32 + lane];
        #pragma unroll
        for (int i = 0; i < 8; i++) xv1[i] = xs1[i * 32 + lane];
    }

    // ---- W A-fragments -> regs (overlaps x-load latency) ----
    uint4 Wf[8];
    {
        const uint4* p = g_Wf + lane;
        #pragma unroll
        for (int f = 0; f < 8; f++) Wf[f] = __ldg(p + f * 32);
    }

    // ---- stage x to smem ----
    #pragma unroll
    for (int i = 0; i < 8; i++) {
        int a = 4 * i + (lane >> 3), b = 4 * (lane & 7);
        uint2 pk;
        pk.x = pk2(xv0[i].x, xv0[i].y);
        pk.y = pk2(xv0[i].z, xv0[i].w);
        *reinterpret_cast<uint2*>(smem + SM_X + (2 * wid) * 2560 + a * 80 + b * 2) = pk;
        pk.x = pk2(xv1[i].x, xv1[i].y);
        pk.y = pk2(xv1[i].z, xv1[i].w);
        *reinterpret_cast<uint2*>(smem + SM_X + (2 * wid + 1) * 2560 + a * 80 + b * 2) = pk;
    }

    // ---- zero P-halves of PQ rows rp=0 and rp=32 (all 8 signals) ----
    {
        int s = tid >> 4;
        int w16 = tid & 15;
        int u = 4 * w16;
        uint32_t off = (uint32_t)(s * 128 + (((u >> 4) ^ (s & 7)) << 4) + (u & 15));
        sts32(sb + SM_PQ + off, 0u);
        sts32(sb + SM_PQ + 32 * PQ_PITCH + off, 0u);
    }

    __syncwarp();

    // ================= Stage 1: warp = 2 signals, 4 mi tiles =================
    const int g = lane >> 2, t4 = lane & 3;
    #pragma unroll
    for (int ss = 0; ss < 2; ss++) {
        const int s = 2 * wid + ss;
        uint32_t bf[2][4][2];
        #pragma unroll
        for (int ks = 0; ks < 2; ks++)
            #pragma unroll
            for (int n16 = 0; n16 < 2; n16++) {
                int a = ks * 16 + (lane & 15);
                uint32_t addr = sb + SM_X + (uint32_t)(s * 2560 + a * 80
                              + (n16 * 16 + (lane >> 4) * 8) * 2);
                uint32_t t[4];
                ldm_x4_t(t, addr);
                bf[ks][n16 * 2 + 0][0] = t[0]; bf[ks][n16 * 2 + 0][1] = t[1];
                bf[ks][n16 * 2 + 1][0] = t[2]; bf[ks][n16 * 2 + 1][1] = t[3];
            }
        #pragma unroll
        for (int mi = 0; mi < 4; mi++) {
            float acc[4][4];
            #pragma unroll
            for (int n8 = 0; n8 < 4; n8++)
                #pragma unroll
                for (int q = 0; q < 4; q++) acc[n8][q] = 0.0f;
            #pragma unroll
            for (int ks = 0; ks < 2; ks++) {
                uint32_t af[4] = { Wf[mi * 2 + ks].x, Wf[mi * 2 + ks].y,
                                   Wf[mi * 2 + ks].z, Wf[mi * 2 + ks].w };
                #pragma unroll
                for (int n8 = 0; n8 < 4; n8++)
                    mma_16816(acc[n8], af, bf[ks][n8]);
            }
            #pragma unroll
            for (int n8 = 0; n8 < 4; n8++)
                #pragma unroll
                for (int ch = 0; ch < 2; ch++) {
                    int fp = mi * 16 + g + (ch << 3);
                    int f  = (fp == 63) ? 65 : fp + 1;
                    int b  = n8 * 8 + 2 * t4;
                    int rp = f >> 1, pq = f & 1;
                    int u  = pq * 64 + 2 * b;
                    uint32_t addr = sb + SM_PQ + (uint32_t)(rp * PQ_PITCH + s * 128
                                  + (((u >> 4) ^ (s & 7)) << 4) + (u & 15));
                    sts32(addr, pk2(acc[n8][2 * ch], acc[n8][2 * ch + 1]));
                }
        }
    }

    // ---- A3 table fragments -> regs (once; overlaps PQ barrier) ----
    uint4 A3[4];
    {
        const uint4* p = g_A3 + lane;
        A3[0] = __ldg(p);      A3[1] = __ldg(p + 32);
        A3[2] = __ldg(p + 64); A3[3] = __ldg(p + 96);
    }

    __syncthreads();   // PQ complete; x buffer dead -> y staging (fp16 chunks)

    // ================= Stage 2: mirror-rp pairing =================
    // Warp w: A-group R = 8w+1..8w+8, B-group R = 57-8w..64-8w (rp = 64-R).
    const uint32_t boct0 = (uint32_t)(((lane >> 3) ^ (lane & 7)) << 4);
    const uint32_t boct1 = (uint32_t)((((lane >> 3) + 4) ^ (lane & 7)) << 4);
    const uint32_t brow  = (uint32_t)((lane & 7) * 128);

    float accA[8][4], accB[8][4];
    #pragma unroll
    for (int e = 0; e < 8; e++)
        #pragma unroll
        for (int q = 0; q < 4; q++) { accA[e][q] = 0.0f; accB[e][q] = 0.0f; }

    #pragma unroll
    for (int i = 0; i <= 8; i++) {
        int rp = 8 * wid + i;

        uint32_t bq[8];
        uint32_t pqb = sb + SM_PQ + (uint32_t)(rp * PQ_PITCH) + brow;
        ldm_x4(bq,     pqb + boct0);
        ldm_x4(bq + 4, pqb + boct1);

        if (i > 0)   // A residue: R = rp
            residue_mma(accA[i - 1], bq, A3, rp, t4);
        if (i < 8)   // B residue: R = 64 - rp
            residue_mma(accB[7 - i], bq, A3, 64 - rp, t4);
    }

    // pack + store staging (fp16 chunks)
    #pragma unroll
    for (int gi = 0; gi < 2; gi++)
        #pragma unroll
        for (int sc = 0; sc < 2; sc++) {
            int cc   = gi * 2 + sc;
            int grow = g + 8 * gi;
            int s    = 2 * t4 + sc;
            uint32_t LA = (uint32_t)(8 * grow + wid);
            uint32_t physA = LA ^ (uint32_t)(s & 7) ^ ((LA >> 3) & 7u);
            sts128(sb + SM_X + (uint32_t)(s * 2048) + physA * 16,
                   pk2(accA[0][cc], accA[1][cc]), pk2(accA[2][cc], accA[3][cc]),
                   pk2(accA[4][cc], accA[5][cc]), pk2(accA[6][cc], accA[7][cc]));
            uint32_t LB = (uint32_t)(8 * grow + 7 - wid);
            uint32_t physB = LB ^ (uint32_t)(s & 7) ^ ((LB >> 3) & 7u);
            sts128(sb + SM_X + (uint32_t)(s * 2048) + physB * 16,
                   pk2(accB[0][cc], accB[1][cc]), pk2(accB[2][cc], accB[3][cc]),
                   pk2(accB[4][cc], accB[5][cc]), pk2(accB[6][cc], accB[7][cc]));
        }

    __syncthreads();

    // ---- copy-out: fp16 staging -> fp32 gmem, fully coalesced ----
    #pragma unroll
    for (int i = 0; i < 16; i++) {
        int flat = i * THREADS + tid;
        int s  = flat >> 8;
        int f4 = flat & 255;
        uint32_t L = (uint32_t)(f4 >> 1);
        uint32_t half = (uint32_t)(f4 & 1);
        uint32_t phys = L ^ (uint32_t)(s & 7) ^ ((L >> 3) & 7u);
        uint32_t lo, hi;
        lds64(sb + SM_X + (uint32_t)(s * 2048) + phys * 16 + half * 8, lo, hi);
        __half2 hl = h2(lo);
        __half2 hh = h2(hi);
        float2 f0 = __half22float2(hl);
        float2 f1 = __half22float2(hh);
        float4 v = make_float4(f0.x, f0.y, f1.x, f1.y);
        *reinterpret_cast<float4*>(y + (s_base + s) * 1024 + f4 * 4) = v;
    }
}

// ============================================================
// Launch
// ============================================================
extern "C" void kernel_launch(void* const* d_in, const int* in_sizes, int n_in,
                              void* d_out, int out_size) {
    const float* x = (const float*)d_in[0];
    float* y = (float*)d_out;

    build_basis_kernel<<<44, 32>>>();

    cudaFuncSetAttribute(dst_fused_kernel,
                         cudaFuncAttributeMaxDynamicSharedMemorySize, SMEM_TOTAL);
    dst_fused_kernel<<<BATCH / SIGS, THREADS, SMEM_TOTAL>>>(x, y);
}